// round 13
// baseline (speedup 1.0000x reference)
#include <cuda_runtime.h>
#include <cuda_bf16.h>

// PackedAvgPool1d — fused streaming kernel, warp-local index prologue,
// host-dispatched fast path (batch <= 32) vs generic path.
//   Fast path: blockDim = 512; 2 warps per output row (8 rows per block);
//   each lane owns 3 float4 columns: half*96 + lane + 32*i, i<3.
//   (DIM=768 -> 192 float4/row; 6 LDG.128 + 3 STG.128 per thread.)
//   Prologue: lane i holds seq_lens[i]; shfl-scan prefixes in registers;
//   row->batch via ballot+popc. No smem, no __syncthreads, 32-bit indexing,
//   no IDIV for S==2. 3 blocks/SM = 48 warps/SM (measured optimum R7-R12).

#define POOL_D4   192
#define MAX_BATCH 1024
#define FULLMASK  0xFFFFFFFFu

__device__ __forceinline__ int pool_ylen(int L, int K, int S)
{
    if (L <= 0) return 0;
    int num = L - K; if (num < 0) num = 0;
    if (S == 2) return ((num + 1) >> 1) + 1;       // dominant case, no IDIV
    return (num + S - 1) / S + 1;
}

__global__ void __launch_bounds__(512, 3) pool_kernel_fast(
    const float4* __restrict__ x,
    const int*    __restrict__ seq_lens,
    const int*    __restrict__ pK,
    const int*    __restrict__ pS,
    float4*       __restrict__ out,
    int batch, int n_rows)
{
    const int lane = threadIdx.x & 31;
    const int warp = threadIdx.x >> 5;             // 0..15

    const int K = pK ? __ldg(pK) : 2;
    const int S = pS ? __ldg(pS) : 2;

    const int row  = blockIdx.x * 8 + (warp >> 1); // 8 rows per block
    const unsigned half = (unsigned)(warp & 1);    // which 96-col half
    const unsigned c    = half * 96u + (unsigned)lane;

    // ---- warp-local prologue ----
    int L = (lane < batch) ? __ldg(&seq_lens[lane]) : 0;
    const int yl = pool_ylen(L, K, S);
    int xs = L, ys = yl;                           // inclusive scans
    #pragma unroll
    for (int d = 1; d < 32; d <<= 1) {
        const int nx = __shfl_up_sync(FULLMASK, xs, d);
        const int ny = __shfl_up_sync(FULLMASK, ys, d);
        if (lane >= d) { xs += nx; ys += ny; }
    }
    if (row >= n_rows) return;                     // uniform per warp
    const unsigned m = __ballot_sync(FULLMASK, ys <= row);
    const int b = __popc(m);
    const int ybase = (b > 0) ? __shfl_sync(FULLMASK, ys, b - 1) : 0;
    const int base  = (b > 0) ? __shfl_sync(FULLMASK, xs, b - 1) : 0;
    const int Lb    = __shfl_sync(FULLMASK, L, b);
    const int j     = row - ybase;

    const int p0 = j * S;
    int cnt = Lb - p0; if (cnt > K) cnt = K; if (cnt < 1) cnt = 1;

    const unsigned sbase = (unsigned)(base + p0) * POOL_D4 + c;
    float4 a[3];
    #pragma unroll
    for (int i = 0; i < 3; ++i)
        a[i] = __ldcs(&x[sbase + 32u * i]);        // 3 front-batched LDG.128

    if (cnt >= 2) {
        float4 v[3];
        #pragma unroll
        for (int i = 0; i < 3; ++i)
            v[i] = __ldcs(&x[sbase + POOL_D4 + 32u * i]);
        if (cnt == 2) {
            #pragma unroll
            for (int i = 0; i < 3; ++i) {
                a[i].x = (a[i].x + v[i].x) * 0.5f;
                a[i].y = (a[i].y + v[i].y) * 0.5f;
                a[i].z = (a[i].z + v[i].z) * 0.5f;
                a[i].w = (a[i].w + v[i].w) * 0.5f;
            }
        } else {                                   // general K (cnt > 2)
            #pragma unroll
            for (int i = 0; i < 3; ++i) {
                a[i].x += v[i].x; a[i].y += v[i].y;
                a[i].z += v[i].z; a[i].w += v[i].w;
            }
            for (int k = 2; k < cnt; ++k) {
                #pragma unroll
                for (int i = 0; i < 3; ++i) {
                    const float4 w = __ldcs(&x[sbase + (unsigned)k * POOL_D4 + 32u * i]);
                    a[i].x += w.x; a[i].y += w.y; a[i].z += w.z; a[i].w += w.w;
                }
            }
            const float inv = 1.0f / (float)cnt;
            #pragma unroll
            for (int i = 0; i < 3; ++i) {
                a[i].x *= inv; a[i].y *= inv; a[i].z *= inv; a[i].w *= inv;
            }
        }
    }

    const unsigned obase = (unsigned)row * POOL_D4 + c;
    #pragma unroll
    for (int i = 0; i < 3; ++i)
        __stcs(&out[obase + 32u * i], a[i]);
}

// ---- generic path (batch > 32): block-shared prefix tables ----
__global__ void __launch_bounds__(384) pool_kernel_generic(
    const float4* __restrict__ x,
    const int*    __restrict__ seq_lens,
    const int*    __restrict__ pK,
    const int*    __restrict__ pS,
    float4*       __restrict__ out,
    int batch, int n_rows)
{
    __shared__ int s_xcu[MAX_BATCH + 1];
    __shared__ int s_ycu[MAX_BATCH + 1];

    const int lane = threadIdx.x & 31;
    const int warp = threadIdx.x >> 5;

    const int K = pK ? __ldg(pK) : 2;
    const int S = pS ? __ldg(pS) : 2;

    if (warp == 0) {
        int xoff = 0, yoff = 0;
        if (lane == 0) { s_xcu[0] = 0; s_ycu[0] = 0; }
        for (int chunk = 0; chunk < batch; chunk += 32) {
            const int i = chunk + lane;
            int L = (i < batch) ? __ldg(&seq_lens[i]) : 0;
            int yl = pool_ylen(L, K, S);
            int xs = L, ys = yl;
            #pragma unroll
            for (int d = 1; d < 32; d <<= 1) {
                const int nx = __shfl_up_sync(FULLMASK, xs, d);
                const int ny = __shfl_up_sync(FULLMASK, ys, d);
                if (lane >= d) { xs += nx; ys += ny; }
            }
            if (i < batch) { s_xcu[i + 1] = xoff + xs; s_ycu[i + 1] = yoff + ys; }
            xoff += __shfl_sync(FULLMASK, xs, 31);
            yoff += __shfl_sync(FULLMASK, ys, 31);
        }
    }
    __syncthreads();

    const int row = blockIdx.x * 4 + warp / 3;
    if (row >= n_rows) return;
    const unsigned c = (unsigned)(warp % 3) * 32u + (unsigned)lane;

    int lo = 0, hi = batch;
    while (hi - lo > 1) {
        const int mid = (lo + hi) >> 1;
        if (s_ycu[mid] <= row) lo = mid; else hi = mid;
    }
    const int base = s_xcu[lo];
    const int Lb   = s_xcu[lo + 1] - base;
    const int j    = row - s_ycu[lo];

    const int p0 = j * S;
    int cnt = Lb - p0; if (cnt > K) cnt = K; if (cnt < 1) cnt = 1;

    const size_t sbase = (size_t)(base + p0) * POOL_D4 + c;
    float4 a0 = __ldcs(&x[sbase]);
    float4 a1 = __ldcs(&x[sbase + 96]);
    if (cnt >= 2) {
        float4 b0 = __ldcs(&x[sbase + POOL_D4]);
        float4 b1 = __ldcs(&x[sbase + POOL_D4 + 96]);
        if (cnt == 2) {
            a0.x = (a0.x + b0.x) * 0.5f; a0.y = (a0.y + b0.y) * 0.5f;
            a0.z = (a0.z + b0.z) * 0.5f; a0.w = (a0.w + b0.w) * 0.5f;
            a1.x = (a1.x + b1.x) * 0.5f; a1.y = (a1.y + b1.y) * 0.5f;
            a1.z = (a1.z + b1.z) * 0.5f; a1.w = (a1.w + b1.w) * 0.5f;
        } else {
            a0.x += b0.x; a0.y += b0.y; a0.z += b0.z; a0.w += b0.w;
            a1.x += b1.x; a1.y += b1.y; a1.z += b1.z; a1.w += b1.w;
            for (int k = 2; k < cnt; ++k) {
                const float4 v0 = __ldcs(&x[sbase + (size_t)k * POOL_D4]);
                const float4 v1 = __ldcs(&x[sbase + (size_t)k * POOL_D4 + 96]);
                a0.x += v0.x; a0.y += v0.y; a0.z += v0.z; a0.w += v0.w;
                a1.x += v1.x; a1.y += v1.y; a1.z += v1.z; a1.w += v1.w;
            }
            const float inv = 1.0f / (float)cnt;
            a0.x *= inv; a0.y *= inv; a0.z *= inv; a0.w *= inv;
            a1.x *= inv; a1.y *= inv; a1.z *= inv; a1.w *= inv;
        }
    }
    const size_t obase = (size_t)row * POOL_D4 + c;
    __stcs(&out[obase], a0);
    __stcs(&out[obase + 96], a1);
}

extern "C" void kernel_launch(void* const* d_in, const int* in_sizes, int n_in,
                              void* d_out, int out_size)
{
    const float4* x        = (const float4*)d_in[0];
    const int*    seq_lens = (const int*)d_in[1];
    const int*    pK       = (n_in >= 3) ? (const int*)d_in[2] : nullptr;
    const int*    pS       = (n_in >= 4) ? (const int*)d_in[3] : nullptr;
    float4*       out      = (float4*)d_out;

    const int batch  = in_sizes[1];
    const int n_rows = out_size / 768;
    if (n_rows <= 0) return;

    if (batch <= 32) {
        const int grid = (n_rows + 7) / 8;
        pool_kernel_fast<<<grid, 512>>>(x, seq_lens, pK, pS, out, batch, n_rows);
    } else {
        const int grid = (n_rows + 3) / 4;
        pool_kernel_generic<<<grid, 384>>>(x, seq_lens, pK, pS, out, batch, n_rows);
    }
}

// round 14
// speedup vs baseline: 1.0077x; 1.0077x over previous
#include <cuda_runtime.h>
#include <cuda_bf16.h>

// PackedAvgPool1d — FINAL configuration (R12 optimum).
//   Fast path (batch <= 32): blockDim = 256; 2 warps per output row
//   (4 rows/block); each lane owns 3 float4 columns: half*96 + lane + 32*i.
//   (DIM=768 -> 192 float4/row; 6 front-batched LDG.128 + 3 STG.128/thread.)
//   Warp-local prologue: lane i holds seq_lens[i]; dual shfl-scan builds
//   x/y prefix sums in registers; row->batch via ballot+popc. No smem, no
//   __syncthreads, 32-bit indexing, no IDIV for S==2, evict-first ld/st.
//   __launch_bounds__(256,6) = 48 warps/SM — measured optimum across
//   R7-R13 sweep (32/40/48/60 warps/SM, 4/6/12 loads/thread):
//   kernel 50.0us, DRAM 82.8% of 8TB/s (mixed-stream ceiling).
//   Generic path (batch > 32): block-shared prefix tables + binary search.

#define POOL_D4   192
#define MAX_BATCH 1024
#define FULLMASK  0xFFFFFFFFu

__device__ __forceinline__ int pool_ylen(int L, int K, int S)
{
    if (L <= 0) return 0;
    int num = L - K; if (num < 0) num = 0;
    if (S == 2) return ((num + 1) >> 1) + 1;       // dominant case, no IDIV
    return (num + S - 1) / S + 1;
}

__global__ void __launch_bounds__(256, 6) pool_kernel_fast(
    const float4* __restrict__ x,
    const int*    __restrict__ seq_lens,
    const int*    __restrict__ pK,
    const int*    __restrict__ pS,
    float4*       __restrict__ out,
    int batch, int n_rows)
{
    const int lane = threadIdx.x & 31;
    const int warp = threadIdx.x >> 5;             // 0..7

    const int K = pK ? __ldg(pK) : 2;
    const int S = pS ? __ldg(pS) : 2;

    const int row  = blockIdx.x * 4 + (warp >> 1); // 4 rows per block
    const unsigned half = (unsigned)(warp & 1);    // which 96-col half
    const unsigned c    = half * 96u + (unsigned)lane;

    // ---- warp-local prologue ----
    int L = (lane < batch) ? __ldg(&seq_lens[lane]) : 0;
    const int yl = pool_ylen(L, K, S);
    int xs = L, ys = yl;                           // inclusive scans
    #pragma unroll
    for (int d = 1; d < 32; d <<= 1) {
        const int nx = __shfl_up_sync(FULLMASK, xs, d);
        const int ny = __shfl_up_sync(FULLMASK, ys, d);
        if (lane >= d) { xs += nx; ys += ny; }
    }
    if (row >= n_rows) return;                     // uniform per warp
    const unsigned m = __ballot_sync(FULLMASK, ys <= row);
    const int b = __popc(m);
    const int ybase = (b > 0) ? __shfl_sync(FULLMASK, ys, b - 1) : 0;
    const int base  = (b > 0) ? __shfl_sync(FULLMASK, xs, b - 1) : 0;
    const int Lb    = __shfl_sync(FULLMASK, L, b);
    const int j     = row - ybase;

    const int p0 = j * S;
    int cnt = Lb - p0; if (cnt > K) cnt = K; if (cnt < 1) cnt = 1;

    const unsigned sbase = (unsigned)(base + p0) * POOL_D4 + c;
    float4 a[3];
    #pragma unroll
    for (int i = 0; i < 3; ++i)
        a[i] = __ldcs(&x[sbase + 32u * i]);        // 3 front-batched LDG.128

    if (cnt >= 2) {
        float4 v[3];
        #pragma unroll
        for (int i = 0; i < 3; ++i)
            v[i] = __ldcs(&x[sbase + POOL_D4 + 32u * i]);
        if (cnt == 2) {
            #pragma unroll
            for (int i = 0; i < 3; ++i) {
                a[i].x = (a[i].x + v[i].x) * 0.5f;
                a[i].y = (a[i].y + v[i].y) * 0.5f;
                a[i].z = (a[i].z + v[i].z) * 0.5f;
                a[i].w = (a[i].w + v[i].w) * 0.5f;
            }
        } else {                                   // general K (cnt > 2)
            #pragma unroll
            for (int i = 0; i < 3; ++i) {
                a[i].x += v[i].x; a[i].y += v[i].y;
                a[i].z += v[i].z; a[i].w += v[i].w;
            }
            for (int k = 2; k < cnt; ++k) {
                #pragma unroll
                for (int i = 0; i < 3; ++i) {
                    const float4 w = __ldcs(&x[sbase + (unsigned)k * POOL_D4 + 32u * i]);
                    a[i].x += w.x; a[i].y += w.y; a[i].z += w.z; a[i].w += w.w;
                }
            }
            const float inv = 1.0f / (float)cnt;
            #pragma unroll
            for (int i = 0; i < 3; ++i) {
                a[i].x *= inv; a[i].y *= inv; a[i].z *= inv; a[i].w *= inv;
            }
        }
    }

    const unsigned obase = (unsigned)row * POOL_D4 + c;
    #pragma unroll
    for (int i = 0; i < 3; ++i)
        __stcs(&out[obase + 32u * i], a[i]);
}

// ---- generic path (batch > 32): block-shared prefix tables ----
__global__ void __launch_bounds__(384) pool_kernel_generic(
    const float4* __restrict__ x,
    const int*    __restrict__ seq_lens,
    const int*    __restrict__ pK,
    const int*    __restrict__ pS,
    float4*       __restrict__ out,
    int batch, int n_rows)
{
    __shared__ int s_xcu[MAX_BATCH + 1];
    __shared__ int s_ycu[MAX_BATCH + 1];

    const int lane = threadIdx.x & 31;
    const int warp = threadIdx.x >> 5;

    const int K = pK ? __ldg(pK) : 2;
    const int S = pS ? __ldg(pS) : 2;

    if (warp == 0) {
        int xoff = 0, yoff = 0;
        if (lane == 0) { s_xcu[0] = 0; s_ycu[0] = 0; }
        for (int chunk = 0; chunk < batch; chunk += 32) {
            const int i = chunk + lane;
            int L = (i < batch) ? __ldg(&seq_lens[i]) : 0;
            int yl = pool_ylen(L, K, S);
            int xs = L, ys = yl;
            #pragma unroll
            for (int d = 1; d < 32; d <<= 1) {
                const int nx = __shfl_up_sync(FULLMASK, xs, d);
                const int ny = __shfl_up_sync(FULLMASK, ys, d);
                if (lane >= d) { xs += nx; ys += ny; }
            }
            if (i < batch) { s_xcu[i + 1] = xoff + xs; s_ycu[i + 1] = yoff + ys; }
            xoff += __shfl_sync(FULLMASK, xs, 31);
            yoff += __shfl_sync(FULLMASK, ys, 31);
        }
    }
    __syncthreads();

    const int row = blockIdx.x * 4 + warp / 3;
    if (row >= n_rows) return;
    const unsigned c = (unsigned)(warp % 3) * 32u + (unsigned)lane;

    int lo = 0, hi = batch;
    while (hi - lo > 1) {
        const int mid = (lo + hi) >> 1;
        if (s_ycu[mid] <= row) lo = mid; else hi = mid;
    }
    const int base = s_xcu[lo];
    const int Lb   = s_xcu[lo + 1] - base;
    const int j    = row - s_ycu[lo];

    const int p0 = j * S;
    int cnt = Lb - p0; if (cnt > K) cnt = K; if (cnt < 1) cnt = 1;

    const size_t sbase = (size_t)(base + p0) * POOL_D4 + c;
    float4 a0 = __ldcs(&x[sbase]);
    float4 a1 = __ldcs(&x[sbase + 96]);
    if (cnt >= 2) {
        float4 b0 = __ldcs(&x[sbase + POOL_D4]);
        float4 b1 = __ldcs(&x[sbase + POOL_D4 + 96]);
        if (cnt == 2) {
            a0.x = (a0.x + b0.x) * 0.5f; a0.y = (a0.y + b0.y) * 0.5f;
            a0.z = (a0.z + b0.z) * 0.5f; a0.w = (a0.w + b0.w) * 0.5f;
            a1.x = (a1.x + b1.x) * 0.5f; a1.y = (a1.y + b1.y) * 0.5f;
            a1.z = (a1.z + b1.z) * 0.5f; a1.w = (a1.w + b1.w) * 0.5f;
        } else {
            a0.x += b0.x; a0.y += b0.y; a0.z += b0.z; a0.w += b0.w;
            a1.x += b1.x; a1.y += b1.y; a1.z += b1.z; a1.w += b1.w;
            for (int k = 2; k < cnt; ++k) {
                const float4 v0 = __ldcs(&x[sbase + (size_t)k * POOL_D4]);
                const float4 v1 = __ldcs(&x[sbase + (size_t)k * POOL_D4 + 96]);
                a0.x += v0.x; a0.y += v0.y; a0.z += v0.z; a0.w += v0.w;
                a1.x += v1.x; a1.y += v1.y; a1.z += v1.z; a1.w += v1.w;
            }
            const float inv = 1.0f / (float)cnt;
            a0.x *= inv; a0.y *= inv; a0.z *= inv; a0.w *= inv;
            a1.x *= inv; a1.y *= inv; a1.z *= inv; a1.w *= inv;
        }
    }
    const size_t obase = (size_t)row * POOL_D4 + c;
    __stcs(&out[obase], a0);
    __stcs(&out[obase + 96], a1);
}

extern "C" void kernel_launch(void* const* d_in, const int* in_sizes, int n_in,
                              void* d_out, int out_size)
{
    const float4* x        = (const float4*)d_in[0];
    const int*    seq_lens = (const int*)d_in[1];
    const int*    pK       = (n_in >= 3) ? (const int*)d_in[2] : nullptr;
    const int*    pS       = (n_in >= 4) ? (const int*)d_in[3] : nullptr;
    float4*       out      = (float4*)d_out;

    const int batch  = in_sizes[1];
    const int n_rows = out_size / 768;
    if (n_rows <= 0) return;

    if (batch <= 32) {
        const int grid = (n_rows + 3) / 4;
        pool_kernel_fast<<<grid, 256>>>(x, seq_lens, pK, pS, out, batch, n_rows);
    } else {
        const int grid = (n_rows + 3) / 4;
        pool_kernel_generic<<<grid, 384>>>(x, seq_lens, pK, pS, out, batch, n_rows);
    }
}

// round 15
// speedup vs baseline: 1.0083x; 1.0006x over previous
#include <cuda_runtime.h>
#include <cuda_bf16.h>

// PackedAvgPool1d — R12 optimum + single-scan prologue for K=2,S=2.
//   Fast path (batch <= 32): blockDim = 256; 2 warps per output row
//   (4 rows/block); each lane owns 3 float4 columns: half*96 + lane + 32*i.
//   (DIM=768 -> 192 float4/row; 6 front-batched LDG.128 + 3 STG.128/thread.)
//   Prologue: lane i holds seq_lens[i]. For K==2 && S==2 (warp-uniform),
//   only the y-prefix is scanned (5 dependent SHFLs); the x-prefix is
//   recovered arithmetically: L = 2*ceil(L/2) - (L&1)  =>
//   x_cu[b] = 2*y_cu[b] - popc(ballot(L&1) & ((1<<b)-1)).
//   Otherwise: dual scan fallback. row->batch via ballot+popc. No smem,
//   no __syncthreads, 32-bit indexing, evict-first ld/st.
//   __launch_bounds__(256,6) = 48 warps/SM — measured optimum (R7-R14).

#define POOL_D4   192
#define MAX_BATCH 1024
#define FULLMASK  0xFFFFFFFFu

__device__ __forceinline__ int pool_ylen(int L, int K, int S)
{
    if (L <= 0) return 0;
    int num = L - K; if (num < 0) num = 0;
    if (S == 2) return ((num + 1) >> 1) + 1;       // no IDIV
    return (num + S - 1) / S + 1;
}

__global__ void __launch_bounds__(256, 6) pool_kernel_fast(
    const float4* __restrict__ x,
    const int*    __restrict__ seq_lens,
    const int*    __restrict__ pK,
    const int*    __restrict__ pS,
    float4*       __restrict__ out,
    int batch, int n_rows)
{
    const int lane = threadIdx.x & 31;
    const int warp = threadIdx.x >> 5;             // 0..7

    const int K = pK ? __ldg(pK) : 2;
    const int S = pS ? __ldg(pS) : 2;

    const int row  = blockIdx.x * 4 + (warp >> 1); // 4 rows per block
    const unsigned half = (unsigned)(warp & 1);    // which 96-col half
    const unsigned c    = half * 96u + (unsigned)lane;

    // ---- warp-local prologue ----
    const int L = (lane < batch) ? __ldg(&seq_lens[lane]) : 0;

    int base, Lb, j;
    if (K == 2 && S == 2) {
        // yl = ceil(L/2); single scan, x-prefix derived from y-prefix.
        int ys = (L + 1) >> 1;
        #pragma unroll
        for (int d = 1; d < 32; d <<= 1) {
            const int ny = __shfl_up_sync(FULLMASK, ys, d);
            if (lane >= d) ys += ny;
        }
        if (row >= n_rows) return;                 // uniform per warp
        const unsigned odd = __ballot_sync(FULLMASK, L & 1);
        const unsigned m   = __ballot_sync(FULLMASK, ys <= row);
        const int b = __popc(m);                   // b <= 31 for valid rows
        const int ybase = (b > 0) ? __shfl_sync(FULLMASK, ys, b - 1) : 0;
        base = 2 * ybase - (int)__popc(odd & (b > 0 ? ((1u << b) - 1u) : 0u));
        Lb   = __shfl_sync(FULLMASK, L, b);
        j    = row - ybase;
    } else {
        const int yl = pool_ylen(L, K, S);
        int xs = L, ys = yl;                       // dual inclusive scans
        #pragma unroll
        for (int d = 1; d < 32; d <<= 1) {
            const int nx = __shfl_up_sync(FULLMASK, xs, d);
            const int ny = __shfl_up_sync(FULLMASK, ys, d);
            if (lane >= d) { xs += nx; ys += ny; }
        }
        if (row >= n_rows) return;
        const unsigned m = __ballot_sync(FULLMASK, ys <= row);
        const int b = __popc(m);
        const int ybase = (b > 0) ? __shfl_sync(FULLMASK, ys, b - 1) : 0;
        base = (b > 0) ? __shfl_sync(FULLMASK, xs, b - 1) : 0;
        Lb   = __shfl_sync(FULLMASK, L, b);
        j    = row - ybase;
    }

    const int p0 = j * S;
    int cnt = Lb - p0; if (cnt > K) cnt = K; if (cnt < 1) cnt = 1;

    const unsigned sbase = (unsigned)(base + p0) * POOL_D4 + c;
    float4 a[3];
    #pragma unroll
    for (int i = 0; i < 3; ++i)
        a[i] = __ldcs(&x[sbase + 32u * i]);        // 3 front-batched LDG.128

    if (cnt >= 2) {
        float4 v[3];
        #pragma unroll
        for (int i = 0; i < 3; ++i)
            v[i] = __ldcs(&x[sbase + POOL_D4 + 32u * i]);
        if (cnt == 2) {
            #pragma unroll
            for (int i = 0; i < 3; ++i) {
                a[i].x = (a[i].x + v[i].x) * 0.5f;
                a[i].y = (a[i].y + v[i].y) * 0.5f;
                a[i].z = (a[i].z + v[i].z) * 0.5f;
                a[i].w = (a[i].w + v[i].w) * 0.5f;
            }
        } else {                                   // general K (cnt > 2)
            #pragma unroll
            for (int i = 0; i < 3; ++i) {
                a[i].x += v[i].x; a[i].y += v[i].y;
                a[i].z += v[i].z; a[i].w += v[i].w;
            }
            for (int k = 2; k < cnt; ++k) {
                #pragma unroll
                for (int i = 0; i < 3; ++i) {
                    const float4 w = __ldcs(&x[sbase + (unsigned)k * POOL_D4 + 32u * i]);
                    a[i].x += w.x; a[i].y += w.y; a[i].z += w.z; a[i].w += w.w;
                }
            }
            const float inv = 1.0f / (float)cnt;
            #pragma unroll
            for (int i = 0; i < 3; ++i) {
                a[i].x *= inv; a[i].y *= inv; a[i].z *= inv; a[i].w *= inv;
            }
        }
    }

    const unsigned obase = (unsigned)row * POOL_D4 + c;
    #pragma unroll
    for (int i = 0; i < 3; ++i)
        __stcs(&out[obase + 32u * i], a[i]);
}

// ---- generic path (batch > 32): block-shared prefix tables ----
__global__ void __launch_bounds__(384) pool_kernel_generic(
    const float4* __restrict__ x,
    const int*    __restrict__ seq_lens,
    const int*    __restrict__ pK,
    const int*    __restrict__ pS,
    float4*       __restrict__ out,
    int batch, int n_rows)
{
    __shared__ int s_xcu[MAX_BATCH + 1];
    __shared__ int s_ycu[MAX_BATCH + 1];

    const int lane = threadIdx.x & 31;
    const int warp = threadIdx.x >> 5;

    const int K = pK ? __ldg(pK) : 2;
    const int S = pS ? __ldg(pS) : 2;

    if (warp == 0) {
        int xoff = 0, yoff = 0;
        if (lane == 0) { s_xcu[0] = 0; s_ycu[0] = 0; }
        for (int chunk = 0; chunk < batch; chunk += 32) {
            const int i = chunk + lane;
            int L = (i < batch) ? __ldg(&seq_lens[i]) : 0;
            int yl = pool_ylen(L, K, S);
            int xs = L, ys = yl;
            #pragma unroll
            for (int d = 1; d < 32; d <<= 1) {
                const int nx = __shfl_up_sync(FULLMASK, xs, d);
                const int ny = __shfl_up_sync(FULLMASK, ys, d);
                if (lane >= d) { xs += nx; ys += ny; }
            }
            if (i < batch) { s_xcu[i + 1] = xoff + xs; s_ycu[i + 1] = yoff + ys; }
            xoff += __shfl_sync(FULLMASK, xs, 31);
            yoff += __shfl_sync(FULLMASK, ys, 31);
        }
    }
    __syncthreads();

    const int row = blockIdx.x * 4 + warp / 3;
    if (row >= n_rows) return;
    const unsigned c = (unsigned)(warp % 3) * 32u + (unsigned)lane;

    int lo = 0, hi = batch;
    while (hi - lo > 1) {
        const int mid = (lo + hi) >> 1;
        if (s_ycu[mid] <= row) lo = mid; else hi = mid;
    }
    const int base = s_xcu[lo];
    const int Lb   = s_xcu[lo + 1] - base;
    const int j    = row - s_ycu[lo];

    const int p0 = j * S;
    int cnt = Lb - p0; if (cnt > K) cnt = K; if (cnt < 1) cnt = 1;

    const size_t sbase = (size_t)(base + p0) * POOL_D4 + c;
    float4 a0 = __ldcs(&x[sbase]);
    float4 a1 = __ldcs(&x[sbase + 96]);
    if (cnt >= 2) {
        float4 b0 = __ldcs(&x[sbase + POOL_D4]);
        float4 b1 = __ldcs(&x[sbase + POOL_D4 + 96]);
        if (cnt == 2) {
            a0.x = (a0.x + b0.x) * 0.5f; a0.y = (a0.y + b0.y) * 0.5f;
            a0.z = (a0.z + b0.z) * 0.5f; a0.w = (a0.w + b0.w) * 0.5f;
            a1.x = (a1.x + b1.x) * 0.5f; a1.y = (a1.y + b1.y) * 0.5f;
            a1.z = (a1.z + b1.z) * 0.5f; a1.w = (a1.w + b1.w) * 0.5f;
        } else {
            a0.x += b0.x; a0.y += b0.y; a0.z += b0.z; a0.w += b0.w;
            a1.x += b1.x; a1.y += b1.y; a1.z += b1.z; a1.w += b1.w;
            for (int k = 2; k < cnt; ++k) {
                const float4 v0 = __ldcs(&x[sbase + (size_t)k * POOL_D4]);
                const float4 v1 = __ldcs(&x[sbase + (size_t)k * POOL_D4 + 96]);
                a0.x += v0.x; a0.y += v0.y; a0.z += v0.z; a0.w += v0.w;
                a1.x += v1.x; a1.y += v1.y; a1.z += v1.z; a1.w += v1.w;
            }
            const float inv = 1.0f / (float)cnt;
            a0.x *= inv; a0.y *= inv; a0.z *= inv; a0.w *= inv;
            a1.x *= inv; a1.y *= inv; a1.z *= inv; a1.w *= inv;
        }
    }
    const size_t obase = (size_t)row * POOL_D4 + c;
    __stcs(&out[obase], a0);
    __stcs(&out[obase + 96], a1);
}

extern "C" void kernel_launch(void* const* d_in, const int* in_sizes, int n_in,
                              void* d_out, int out_size)
{
    const float4* x        = (const float4*)d_in[0];
    const int*    seq_lens = (const int*)d_in[1];
    const int*    pK       = (n_in >= 3) ? (const int*)d_in[2] : nullptr;
    const int*    pS       = (n_in >= 4) ? (const int*)d_in[3] : nullptr;
    float4*       out      = (float4*)d_out;

    const int batch  = in_sizes[1];
    const int n_rows = out_size / 768;
    if (n_rows <= 0) return;

    if (batch <= 32) {
        const int grid = (n_rows + 3) / 4;
        pool_kernel_fast<<<grid, 256>>>(x, seq_lens, pK, pS, out, batch, n_rows);
    } else {
        const int grid = (n_rows + 3) / 4;
        pool_kernel_generic<<<grid, 384>>>(x, seq_lens, pK, pS, out, batch, n_rows);
    }
}